// round 1
// baseline (speedup 1.0000x reference)
#include <cuda_runtime.h>
#include <cuda_bf16.h>
#include <math.h>

#define NN 4096            // nodes
#define EE 131072          // edges
#define F  128             // hidden feature width
#define K_ITERS 30         // Richardson iterations; 0.5^30 ~ 1e-9

// ---------------- scratch (static device globals; no allocation) ------------
__device__ int   g_deg[NN];
__device__ int   g_cnt[NN];
__device__ int   g_cur[NN];
__device__ int   g_off[NN + 1];
__device__ float g_dis[NN];            // deg^{-1/2}
__device__ int   g_esrc[EE];
__device__ float g_enorm[EE];
__device__ float g_rhs[3 * NN];        // SoA: col-major, 3 columns of 4096
__device__ float g_xA[3 * NN];
__device__ float g_xB[3 * NN];
__device__ float g_feat[4 * NN];       // row-major [NN,4]
__device__ float g_h1[NN * F];
__device__ float g_h2[NN * F];

// ---------------- graph preprocessing ---------------------------------------
__global__ void k_init() {
    int i = blockIdx.x * blockDim.x + threadIdx.x;
    if (i < NN) { g_deg[i] = 1; g_cnt[i] = 0; g_cur[i] = 0; }   // deg=1: self loop
}

__global__ void k_edges(const int* __restrict__ ei, int E) {
    int e = blockIdx.x * blockDim.x + threadIdx.x;
    if (e < E) {
        int r = ei[e];
        int c = ei[E + e];
        atomicAdd(&g_deg[r], 1);
        atomicAdd(&g_cnt[c], 1);
    }
}

__global__ void k_dis() {
    int i = blockIdx.x * blockDim.x + threadIdx.x;
    if (i < NN) g_dis[i] = rsqrtf((float)g_deg[i]);
}

// single-block exclusive scan of g_cnt[4096] -> g_off[4097]
__global__ void k_scan() {
    __shared__ int wsum[32];
    int t = threadIdx.x;                 // 1024 threads, 4 elems each
    int lane = t & 31, wid = t >> 5;
    int c0 = g_cnt[4 * t], c1 = g_cnt[4 * t + 1], c2 = g_cnt[4 * t + 2], c3 = g_cnt[4 * t + 3];
    int local = c0 + c1 + c2 + c3;
    int v = local;
    #pragma unroll
    for (int o = 1; o < 32; o <<= 1) {
        int u = __shfl_up_sync(0xffffffffu, v, o);
        if (lane >= o) v += u;
    }
    if (lane == 31) wsum[wid] = v;
    __syncthreads();
    if (wid == 0) {
        int w = wsum[lane];
        #pragma unroll
        for (int o = 1; o < 32; o <<= 1) {
            int u = __shfl_up_sync(0xffffffffu, w, o);
            if (lane >= o) w += u;
        }
        wsum[lane] = w;
    }
    __syncthreads();
    int base = v - local + (wid ? wsum[wid - 1] : 0);
    g_off[4 * t]     = base;
    g_off[4 * t + 1] = base + c0;
    g_off[4 * t + 2] = base + c0 + c1;
    g_off[4 * t + 3] = base + c0 + c1 + c2;
    if (t == 1023) g_off[NN] = base + local;
}

__global__ void k_fill(const int* __restrict__ ei, int E) {
    int e = blockIdx.x * blockDim.x + threadIdx.x;
    if (e < E) {
        int r = ei[e];
        int c = ei[E + e];
        int p = g_off[c] + atomicAdd(&g_cur[c], 1);
        g_esrc[p]  = r;
        g_enorm[p] = g_dis[r] * g_dis[c];
    }
}

// ---------------- LPSI solve -------------------------------------------------
__global__ void k_rhs(const float* __restrict__ dv, const float* __restrict__ thrp) {
    int i = blockIdx.x * blockDim.x + threadIdx.x;
    if (i < NN) {
        float t = *thrp;
        float d = dv[i];
        float r0 = d, r1 = fmaxf(d, t), r2 = fminf(d, t);
        g_rhs[i] = r0;          g_rhs[NN + i] = r1;          g_rhs[2 * NN + i] = r2;
        g_xA[i]  = r0;          g_xA[NN + i]  = r1;          g_xA[2 * NN + i]  = r2;
        g_feat[4 * i] = d;
    }
}

// x_out = rhs + alpha * L @ x_in   (3 columns, SoA). warp-per-row GEMV.
__global__ void __launch_bounds__(256) k_rich(const float* __restrict__ L,
                                              const float* __restrict__ xin,
                                              float* __restrict__ xout,
                                              const float* __restrict__ alphap) {
    __shared__ float sx[3 * NN];                       // 48 KB
    const float4* xin4 = (const float4*)xin;
    for (int idx = threadIdx.x; idx < (3 * NN) / 4; idx += 256)
        ((float4*)sx)[idx] = xin4[idx];
    __syncthreads();

    int warp = threadIdx.x >> 5, lane = threadIdx.x & 31;
    int r = (blockIdx.x << 3) + warp;                  // 512 blocks * 8 warps = 4096
    const float4* Lr = (const float4*)(L + (size_t)r * NN);
    float a0 = 0.f, a1 = 0.f, a2 = 0.f;
    #pragma unroll 4
    for (int t = 0; t < 32; ++t) {
        int j4 = lane + (t << 5);
        float4 lv = Lr[j4];
        int b = j4 << 2;
        float4 x0 = *(const float4*)(sx + b);
        float4 x1 = *(const float4*)(sx + NN + b);
        float4 x2 = *(const float4*)(sx + 2 * NN + b);
        a0 += lv.x * x0.x + lv.y * x0.y + lv.z * x0.z + lv.w * x0.w;
        a1 += lv.x * x1.x + lv.y * x1.y + lv.z * x1.z + lv.w * x1.w;
        a2 += lv.x * x2.x + lv.y * x2.y + lv.z * x2.z + lv.w * x2.w;
    }
    #pragma unroll
    for (int o = 16; o; o >>= 1) {
        a0 += __shfl_down_sync(0xffffffffu, a0, o);
        a1 += __shfl_down_sync(0xffffffffu, a1, o);
        a2 += __shfl_down_sync(0xffffffffu, a2, o);
    }
    if (lane == 0) {
        float al = *alphap;
        xout[r]          = g_rhs[r]          + al * a0;
        xout[NN + r]     = g_rhs[NN + r]     + al * a1;
        xout[2 * NN + r] = g_rhs[2 * NN + r] + al * a2;
    }
}

__global__ void k_featfin(const float* __restrict__ xfin, const float* __restrict__ alphap) {
    int i = blockIdx.x * blockDim.x + threadIdx.x;
    if (i < NN) {
        float s = 1.0f - *alphap;
        g_feat[4 * i + 1] = s * xfin[i];
        g_feat[4 * i + 2] = s * xfin[NN + i];
        g_feat[4 * i + 3] = s * xfin[2 * NN + i];
    }
}

// ---------------- GCN layers -------------------------------------------------
__global__ void k_lin1(const float* __restrict__ w1, const float* __restrict__ b1) {
    int id = blockIdx.x * blockDim.x + threadIdx.x;    // NN*F threads
    if (id < NN * F) {
        int i = id >> 7, f = id & 127;
        float acc = b1[f];
        #pragma unroll
        for (int c = 0; c < 4; ++c)
            acc += g_feat[4 * i + c] * w1[c * F + f];
        g_h1[id] = acc;
    }
}

__global__ void __launch_bounds__(128) k_aggr(const float* __restrict__ hin,
                                              float* __restrict__ hout, int relu) {
    int i = blockIdx.x;
    int f = threadIdx.x;
    float d = g_dis[i];
    float acc = d * d * hin[i * F + f];                // self loop
    int e = g_off[i], end = g_off[i + 1];
    for (; e + 4 <= end; e += 4) {
        int   s0 = g_esrc[e],     s1 = g_esrc[e + 1], s2 = g_esrc[e + 2], s3 = g_esrc[e + 3];
        float n0 = g_enorm[e],    n1 = g_enorm[e + 1], n2 = g_enorm[e + 2], n3 = g_enorm[e + 3];
        acc += n0 * hin[s0 * F + f] + n1 * hin[s1 * F + f]
             + n2 * hin[s2 * F + f] + n3 * hin[s3 * F + f];
    }
    for (; e < end; ++e)
        acc += g_enorm[e] * hin[g_esrc[e] * F + f];
    if (relu) acc = fmaxf(acc, 0.0f);
    hout[i * F + f] = acc;
}

__global__ void k_lin2(const float* __restrict__ hin, float* __restrict__ hout,
                       const float* __restrict__ w2, const float* __restrict__ b2) {
    int id = blockIdx.x * blockDim.x + threadIdx.x;
    if (id < NN * F) {
        int i = id >> 7, f = id & 127;
        const float* hr = hin + i * F;
        float acc = b2[f];
        #pragma unroll 8
        for (int g = 0; g < F; ++g)
            acc += hr[g] * w2[g * F + f];
        hout[id] = acc;
    }
}

__global__ void k_final(const float* __restrict__ hin, const float* __restrict__ wf,
                        const float* __restrict__ bf, float* __restrict__ out) {
    int gid = blockIdx.x * blockDim.x + threadIdx.x;
    int node = gid >> 5, lane = gid & 31;
    if (node < NN) {
        float a0 = 0.f, a1 = 0.f;
        #pragma unroll
        for (int f = lane; f < F; f += 32) {
            float h = hin[node * F + f];
            a0 += h * wf[2 * f];
            a1 += h * wf[2 * f + 1];
        }
        #pragma unroll
        for (int o = 16; o; o >>= 1) {
            a0 += __shfl_down_sync(0xffffffffu, a0, o);
            a1 += __shfl_down_sync(0xffffffffu, a1, o);
        }
        if (lane == 0) {
            out[2 * node]     = a0 + bf[0];
            out[2 * node + 1] = a1 + bf[1];
        }
    }
}

// ---------------- driver -----------------------------------------------------
extern "C" void kernel_launch(void* const* d_in, const int* in_sizes, int n_in,
                              void* d_out, int out_size) {
    const float* alpha = (const float*)d_in[0];
    const float* L     = (const float*)d_in[1];
    const float* thr   = (const float*)d_in[2];
    const float* dv    = (const float*)d_in[3];
    const int*   ei    = (const int*)  d_in[4];
    const float* w1    = (const float*)d_in[5];
    const float* b1    = (const float*)d_in[6];
    const float* w2    = (const float*)d_in[7];
    const float* b2    = (const float*)d_in[8];
    const float* wf    = (const float*)d_in[9];
    const float* bf    = (const float*)d_in[10];
    float* out = (float*)d_out;
    int E = in_sizes[4] / 2;

    float *pa, *pb, *h1, *h2;
    cudaGetSymbolAddress((void**)&pa, g_xA);
    cudaGetSymbolAddress((void**)&pb, g_xB);
    cudaGetSymbolAddress((void**)&h1, g_h1);
    cudaGetSymbolAddress((void**)&h2, g_h2);

    k_init<<<NN / 256, 256>>>();
    k_edges<<<(E + 255) / 256, 256>>>(ei, E);
    k_dis<<<NN / 256, 256>>>();
    k_scan<<<1, 1024>>>();
    k_fill<<<(E + 255) / 256, 256>>>(ei, E);
    k_rhs<<<NN / 256, 256>>>(dv, thr);

    float* cur = pa;
    float* nxt = pb;
    for (int k = 0; k < K_ITERS; ++k) {
        k_rich<<<NN / 8, 256>>>(L, cur, nxt, alpha);
        float* t = cur; cur = nxt; nxt = t;
    }
    k_featfin<<<NN / 256, 256>>>(cur, alpha);

    k_lin1<<<(NN * F) / 256, 256>>>(w1, b1);
    k_aggr<<<NN, 128>>>(h1, h2, 1);
    k_lin2<<<(NN * F) / 256, 256>>>(h2, h1, w2, b2);
    k_aggr<<<NN, 128>>>(h1, h2, 0);
    k_final<<<(NN * 32) / 256, 256>>>(h2, wf, bf, out);
}

// round 2
// speedup vs baseline: 1.9344x; 1.9344x over previous
#include <cuda_runtime.h>
#include <cuda_bf16.h>
#include <math.h>

#define NN 4096            // nodes
#define EE 131072          // edges
#define F  128             // hidden feature width
#define K_ITERS 18         // Richardson iterations; 0.5^18 ~ 3.8e-6 truncation

// ---------------- scratch (static device globals; no allocation) ------------
__device__ int   g_deg[NN];
__device__ int   g_cnt[NN];
__device__ int   g_cur[NN];
__device__ int   g_off[NN + 1];
__device__ float g_dis[NN];            // deg^{-1/2}
__device__ int   g_esrc[EE];
__device__ float g_enorm[EE];
__device__ float g_rhs[3 * NN];        // SoA: 3 columns of 4096
__device__ float g_xA[3 * NN];
__device__ float g_xB[3 * NN];
__device__ float g_feat[4 * NN];       // row-major [NN,4]
__device__ float g_h1[NN * F];
__device__ float g_h2[NN * F];

// ---------------- graph preprocessing ---------------------------------------
__global__ void k_init() {
    int i = blockIdx.x * blockDim.x + threadIdx.x;
    if (i < NN) { g_deg[i] = 1; g_cnt[i] = 0; g_cur[i] = 0; }   // deg=1: self loop
}

__global__ void k_edges(const int* __restrict__ ei, int E) {
    int e = blockIdx.x * blockDim.x + threadIdx.x;
    if (e < E) {
        int r = ei[e];
        int c = ei[E + e];
        atomicAdd(&g_deg[r], 1);
        atomicAdd(&g_cnt[c], 1);
    }
}

__global__ void k_dis() {
    int i = blockIdx.x * blockDim.x + threadIdx.x;
    if (i < NN) g_dis[i] = rsqrtf((float)g_deg[i]);
}

// single-block exclusive scan of g_cnt[4096] -> g_off[4097]
__global__ void k_scan() {
    __shared__ int wsum[32];
    int t = threadIdx.x;                 // 1024 threads, 4 elems each
    int lane = t & 31, wid = t >> 5;
    int c0 = g_cnt[4 * t], c1 = g_cnt[4 * t + 1], c2 = g_cnt[4 * t + 2], c3 = g_cnt[4 * t + 3];
    int local = c0 + c1 + c2 + c3;
    int v = local;
    #pragma unroll
    for (int o = 1; o < 32; o <<= 1) {
        int u = __shfl_up_sync(0xffffffffu, v, o);
        if (lane >= o) v += u;
    }
    if (lane == 31) wsum[wid] = v;
    __syncthreads();
    if (wid == 0) {
        int w = wsum[lane];
        #pragma unroll
        for (int o = 1; o < 32; o <<= 1) {
            int u = __shfl_up_sync(0xffffffffu, w, o);
            if (lane >= o) w += u;
        }
        wsum[lane] = w;
    }
    __syncthreads();
    int base = v - local + (wid ? wsum[wid - 1] : 0);
    g_off[4 * t]     = base;
    g_off[4 * t + 1] = base + c0;
    g_off[4 * t + 2] = base + c0 + c1;
    g_off[4 * t + 3] = base + c0 + c1 + c2;
    if (t == 1023) g_off[NN] = base + local;
}

__global__ void k_fill(const int* __restrict__ ei, int E) {
    int e = blockIdx.x * blockDim.x + threadIdx.x;
    if (e < E) {
        int r = ei[e];
        int c = ei[E + e];
        int p = g_off[c] + atomicAdd(&g_cur[c], 1);
        g_esrc[p]  = r;
        g_enorm[p] = g_dis[r] * g_dis[c];
    }
}

// ---------------- LPSI solve -------------------------------------------------
__global__ void k_rhs(const float* __restrict__ dv, const float* __restrict__ thrp) {
    int i = blockIdx.x * blockDim.x + threadIdx.x;
    if (i < NN) {
        float t = *thrp;
        float d = dv[i];
        float r0 = d, r1 = fmaxf(d, t), r2 = fminf(d, t);
        g_rhs[i] = r0;          g_rhs[NN + i] = r1;          g_rhs[2 * NN + i] = r2;
        g_xA[i]  = r0;          g_xA[NN + i]  = r1;          g_xA[2 * NN + i]  = r2;
        g_feat[4 * i] = d;
    }
}

// x_out = rhs + alpha * L @ x_in   (3 columns, SoA).
// 4 rows per warp: each x float4 from shared is reused across 4 L rows,
// cutting LDS traffic to 0.75 B per B of L (vs 3.0 with warp-per-row).
__global__ void __launch_bounds__(128) k_rich(const float* __restrict__ L,
                                              const float* __restrict__ xin,
                                              float* __restrict__ xout,
                                              const float* __restrict__ alphap) {
    __shared__ float sx[3 * NN];                       // 48 KB
    const float4* xin4 = (const float4*)xin;
    for (int idx = threadIdx.x; idx < (3 * NN) / 4; idx += 128)
        ((float4*)sx)[idx] = xin4[idx];
    __syncthreads();

    int warp = threadIdx.x >> 5, lane = threadIdx.x & 31;
    int r0 = (blockIdx.x << 4) + (warp << 2);          // 256 blocks * 16 rows
    const float4* L0 = (const float4*)(L + (size_t)r0 * NN);
    const float4* L1 = (const float4*)(L + (size_t)(r0 + 1) * NN);
    const float4* L2 = (const float4*)(L + (size_t)(r0 + 2) * NN);
    const float4* L3 = (const float4*)(L + (size_t)(r0 + 3) * NN);

    float a00 = 0.f, a01 = 0.f, a02 = 0.f;
    float a10 = 0.f, a11 = 0.f, a12 = 0.f;
    float a20 = 0.f, a21 = 0.f, a22 = 0.f;
    float a30 = 0.f, a31 = 0.f, a32 = 0.f;

    #pragma unroll 2
    for (int t = 0; t < 32; ++t) {
        int j4 = lane + (t << 5);
        float4 l0 = L0[j4];
        float4 l1 = L1[j4];
        float4 l2 = L2[j4];
        float4 l3 = L3[j4];
        int b = j4 << 2;
        float4 x0 = *(const float4*)(sx + b);
        float4 x1 = *(const float4*)(sx + NN + b);
        float4 x2 = *(const float4*)(sx + 2 * NN + b);

        a00 += l0.x * x0.x + l0.y * x0.y + l0.z * x0.z + l0.w * x0.w;
        a01 += l0.x * x1.x + l0.y * x1.y + l0.z * x1.z + l0.w * x1.w;
        a02 += l0.x * x2.x + l0.y * x2.y + l0.z * x2.z + l0.w * x2.w;

        a10 += l1.x * x0.x + l1.y * x0.y + l1.z * x0.z + l1.w * x0.w;
        a11 += l1.x * x1.x + l1.y * x1.y + l1.z * x1.z + l1.w * x1.w;
        a12 += l1.x * x2.x + l1.y * x2.y + l1.z * x2.z + l1.w * x2.w;

        a20 += l2.x * x0.x + l2.y * x0.y + l2.z * x0.z + l2.w * x0.w;
        a21 += l2.x * x1.x + l2.y * x1.y + l2.z * x1.z + l2.w * x1.w;
        a22 += l2.x * x2.x + l2.y * x2.y + l2.z * x2.z + l2.w * x2.w;

        a30 += l3.x * x0.x + l3.y * x0.y + l3.z * x0.z + l3.w * x0.w;
        a31 += l3.x * x1.x + l3.y * x1.y + l3.z * x1.z + l3.w * x1.w;
        a32 += l3.x * x2.x + l3.y * x2.y + l3.z * x2.z + l3.w * x2.w;
    }

    #pragma unroll
    for (int o = 16; o; o >>= 1) {
        a00 += __shfl_down_sync(0xffffffffu, a00, o);
        a01 += __shfl_down_sync(0xffffffffu, a01, o);
        a02 += __shfl_down_sync(0xffffffffu, a02, o);
        a10 += __shfl_down_sync(0xffffffffu, a10, o);
        a11 += __shfl_down_sync(0xffffffffu, a11, o);
        a12 += __shfl_down_sync(0xffffffffu, a12, o);
        a20 += __shfl_down_sync(0xffffffffu, a20, o);
        a21 += __shfl_down_sync(0xffffffffu, a21, o);
        a22 += __shfl_down_sync(0xffffffffu, a22, o);
        a30 += __shfl_down_sync(0xffffffffu, a30, o);
        a31 += __shfl_down_sync(0xffffffffu, a31, o);
        a32 += __shfl_down_sync(0xffffffffu, a32, o);
    }
    if (lane == 0) {
        float al = *alphap;
        xout[r0]              = g_rhs[r0]              + al * a00;
        xout[NN + r0]         = g_rhs[NN + r0]         + al * a01;
        xout[2 * NN + r0]     = g_rhs[2 * NN + r0]     + al * a02;
        xout[r0 + 1]          = g_rhs[r0 + 1]          + al * a10;
        xout[NN + r0 + 1]     = g_rhs[NN + r0 + 1]     + al * a11;
        xout[2 * NN + r0 + 1] = g_rhs[2 * NN + r0 + 1] + al * a12;
        xout[r0 + 2]          = g_rhs[r0 + 2]          + al * a20;
        xout[NN + r0 + 2]     = g_rhs[NN + r0 + 2]     + al * a21;
        xout[2 * NN + r0 + 2] = g_rhs[2 * NN + r0 + 2] + al * a22;
        xout[r0 + 3]          = g_rhs[r0 + 3]          + al * a30;
        xout[NN + r0 + 3]     = g_rhs[NN + r0 + 3]     + al * a31;
        xout[2 * NN + r0 + 3] = g_rhs[2 * NN + r0 + 3] + al * a32;
    }
}

__global__ void k_featfin(const float* __restrict__ xfin, const float* __restrict__ alphap) {
    int i = blockIdx.x * blockDim.x + threadIdx.x;
    if (i < NN) {
        float s = 1.0f - *alphap;
        g_feat[4 * i + 1] = s * xfin[i];
        g_feat[4 * i + 2] = s * xfin[NN + i];
        g_feat[4 * i + 3] = s * xfin[2 * NN + i];
    }
}

// ---------------- GCN layers -------------------------------------------------
__global__ void k_lin1(const float* __restrict__ w1, const float* __restrict__ b1) {
    int id = blockIdx.x * blockDim.x + threadIdx.x;    // NN*F threads
    if (id < NN * F) {
        int i = id >> 7, f = id & 127;
        float acc = b1[f];
        #pragma unroll
        for (int c = 0; c < 4; ++c)
            acc += g_feat[4 * i + c] * w1[c * F + f];
        g_h1[id] = acc;
    }
}

__global__ void __launch_bounds__(128) k_aggr(const float* __restrict__ hin,
                                              float* __restrict__ hout, int relu) {
    int i = blockIdx.x;
    int f = threadIdx.x;
    float d = g_dis[i];
    float acc = d * d * hin[i * F + f];                // self loop
    int e = g_off[i], end = g_off[i + 1];
    for (; e + 4 <= end; e += 4) {
        int   s0 = g_esrc[e],     s1 = g_esrc[e + 1], s2 = g_esrc[e + 2], s3 = g_esrc[e + 3];
        float n0 = g_enorm[e],    n1 = g_enorm[e + 1], n2 = g_enorm[e + 2], n3 = g_enorm[e + 3];
        acc += n0 * hin[s0 * F + f] + n1 * hin[s1 * F + f]
             + n2 * hin[s2 * F + f] + n3 * hin[s3 * F + f];
    }
    for (; e < end; ++e)
        acc += g_enorm[e] * hin[g_esrc[e] * F + f];
    if (relu) acc = fmaxf(acc, 0.0f);
    hout[i * F + f] = acc;
}

__global__ void k_lin2(const float* __restrict__ hin, float* __restrict__ hout,
                       const float* __restrict__ w2, const float* __restrict__ b2) {
    int id = blockIdx.x * blockDim.x + threadIdx.x;
    if (id < NN * F) {
        int i = id >> 7, f = id & 127;
        const float* hr = hin + i * F;
        float acc = b2[f];
        #pragma unroll 8
        for (int g = 0; g < F; ++g)
            acc += hr[g] * w2[g * F + f];
        hout[id] = acc;
    }
}

__global__ void k_final(const float* __restrict__ hin, const float* __restrict__ wf,
                        const float* __restrict__ bf, float* __restrict__ out) {
    int gid = blockIdx.x * blockDim.x + threadIdx.x;
    int node = gid >> 5, lane = gid & 31;
    if (node < NN) {
        float a0 = 0.f, a1 = 0.f;
        #pragma unroll
        for (int f = lane; f < F; f += 32) {
            float h = hin[node * F + f];
            a0 += h * wf[2 * f];
            a1 += h * wf[2 * f + 1];
        }
        #pragma unroll
        for (int o = 16; o; o >>= 1) {
            a0 += __shfl_down_sync(0xffffffffu, a0, o);
            a1 += __shfl_down_sync(0xffffffffu, a1, o);
        }
        if (lane == 0) {
            out[2 * node]     = a0 + bf[0];
            out[2 * node + 1] = a1 + bf[1];
        }
    }
}

// ---------------- driver -----------------------------------------------------
extern "C" void kernel_launch(void* const* d_in, const int* in_sizes, int n_in,
                              void* d_out, int out_size) {
    const float* alpha = (const float*)d_in[0];
    const float* L     = (const float*)d_in[1];
    const float* thr   = (const float*)d_in[2];
    const float* dv    = (const float*)d_in[3];
    const int*   ei    = (const int*)  d_in[4];
    const float* w1    = (const float*)d_in[5];
    const float* b1    = (const float*)d_in[6];
    const float* w2    = (const float*)d_in[7];
    const float* b2    = (const float*)d_in[8];
    const float* wf    = (const float*)d_in[9];
    const float* bf    = (const float*)d_in[10];
    float* out = (float*)d_out;
    int E = in_sizes[4] / 2;

    float *pa, *pb, *h1, *h2;
    cudaGetSymbolAddress((void**)&pa, g_xA);
    cudaGetSymbolAddress((void**)&pb, g_xB);
    cudaGetSymbolAddress((void**)&h1, g_h1);
    cudaGetSymbolAddress((void**)&h2, g_h2);

    k_init<<<NN / 256, 256>>>();
    k_edges<<<(E + 255) / 256, 256>>>(ei, E);
    k_dis<<<NN / 256, 256>>>();
    k_scan<<<1, 1024>>>();
    k_fill<<<(E + 255) / 256, 256>>>(ei, E);
    k_rhs<<<NN / 256, 256>>>(dv, thr);

    float* cur = pa;
    float* nxt = pb;
    for (int k = 0; k < K_ITERS; ++k) {
        k_rich<<<NN / 16, 128>>>(L, cur, nxt, alpha);
        float* t = cur; cur = nxt; nxt = t;
    }
    k_featfin<<<NN / 256, 256>>>(cur, alpha);

    k_lin1<<<(NN * F) / 256, 256>>>(w1, b1);
    k_aggr<<<NN, 128>>>(h1, h2, 1);
    k_lin2<<<(NN * F) / 256, 256>>>(h2, h1, w2, b2);
    k_aggr<<<NN, 128>>>(h1, h2, 0);
    k_final<<<(NN * 32) / 256, 256>>>(h2, wf, bf, out);
}

// round 3
// speedup vs baseline: 2.1470x; 1.1099x over previous
#include <cuda_runtime.h>
#include <cuda_fp16.h>
#include <cuda_bf16.h>
#include <math.h>

#define NN 4096            // nodes
#define EE 131072          // edges
#define F  128             // hidden feature width
#define K_H   10           // Richardson iterations on fp16 L
#define K_F32 2            // fp32 polish iterations

// ---------------- scratch (static device globals; no allocation) ------------
__device__ int    g_deg[NN];
__device__ int    g_cnt[NN];
__device__ int    g_cur[NN];
__device__ int    g_off[NN + 1];
__device__ float  g_dis[NN];           // deg^{-1/2}
__device__ int    g_esrc[EE];
__device__ float  g_enorm[EE];
__device__ float  g_rhs[3 * NN];       // SoA: 3 columns of 4096
__device__ float  g_xA[3 * NN];
__device__ float  g_xB[3 * NN];
__device__ float  g_h1[NN * F];
__device__ float  g_h2[NN * F];
__device__ __half g_Lh[(size_t)NN * NN];   // fp16 copy of laplacian (32 MB)

// ---------------- graph preprocessing ---------------------------------------
__global__ void k_init() {
    int i = blockIdx.x * blockDim.x + threadIdx.x;
    if (i < NN) { g_deg[i] = 1; g_cnt[i] = 0; g_cur[i] = 0; }   // deg=1: self loop
}

__global__ void k_edges(const int* __restrict__ ei, int E) {
    int e = blockIdx.x * blockDim.x + threadIdx.x;
    if (e < E) {
        int r = ei[e];
        int c = ei[E + e];
        atomicAdd(&g_deg[r], 1);
        atomicAdd(&g_cnt[c], 1);
    }
}

__global__ void k_dis() {
    int i = blockIdx.x * blockDim.x + threadIdx.x;
    if (i < NN) g_dis[i] = rsqrtf((float)g_deg[i]);
}

// single-block exclusive scan of g_cnt[4096] -> g_off[4097]
__global__ void k_scan() {
    __shared__ int wsum[32];
    int t = threadIdx.x;                 // 1024 threads, 4 elems each
    int lane = t & 31, wid = t >> 5;
    int c0 = g_cnt[4 * t], c1 = g_cnt[4 * t + 1], c2 = g_cnt[4 * t + 2], c3 = g_cnt[4 * t + 3];
    int local = c0 + c1 + c2 + c3;
    int v = local;
    #pragma unroll
    for (int o = 1; o < 32; o <<= 1) {
        int u = __shfl_up_sync(0xffffffffu, v, o);
        if (lane >= o) v += u;
    }
    if (lane == 31) wsum[wid] = v;
    __syncthreads();
    if (wid == 0) {
        int w = wsum[lane];
        #pragma unroll
        for (int o = 1; o < 32; o <<= 1) {
            int u = __shfl_up_sync(0xffffffffu, w, o);
            if (lane >= o) w += u;
        }
        wsum[lane] = w;
    }
    __syncthreads();
    int base = v - local + (wid ? wsum[wid - 1] : 0);
    g_off[4 * t]     = base;
    g_off[4 * t + 1] = base + c0;
    g_off[4 * t + 2] = base + c0 + c1;
    g_off[4 * t + 3] = base + c0 + c1 + c2;
    if (t == 1023) g_off[NN] = base + local;
}

__global__ void k_fill(const int* __restrict__ ei, int E) {
    int e = blockIdx.x * blockDim.x + threadIdx.x;
    if (e < E) {
        int r = ei[e];
        int c = ei[E + e];
        int p = g_off[c] + atomicAdd(&g_cur[c], 1);
        g_esrc[p]  = r;
        g_enorm[p] = g_dis[r] * g_dis[c];
    }
}

// ---------------- LPSI solve -------------------------------------------------
__global__ void k_rhs(const float* __restrict__ dv, const float* __restrict__ thrp) {
    int i = blockIdx.x * blockDim.x + threadIdx.x;
    if (i < NN) {
        float t = *thrp;
        float d = dv[i];
        float r0 = d, r1 = fmaxf(d, t), r2 = fminf(d, t);
        g_rhs[i] = r0;          g_rhs[NN + i] = r1;          g_rhs[2 * NN + i] = r2;
        g_xA[i]  = r0;          g_xA[NN + i]  = r1;          g_xA[2 * NN + i]  = r2;
    }
}

// L fp32 -> fp16 (one DRAM pass)
__global__ void __launch_bounds__(256) k_cvt(const float* __restrict__ L) {
    int idx = blockIdx.x * blockDim.x + threadIdx.x;   // one float4 each
    const float4* L4 = (const float4*)L;
    float4 v = L4[idx];
    __half2 h01 = __floats2half2_rn(v.x, v.y);
    __half2 h23 = __floats2half2_rn(v.z, v.w);
    uint2 o;
    o.x = *(const unsigned int*)&h01;
    o.y = *(const unsigned int*)&h23;
    ((uint2*)g_Lh)[idx] = o;
}

// fp16-L Richardson step: x_out = rhs + alpha * Lh @ x_in (3 cols, fp32 accum)
// 8 warps * 4 rows = 32 rows/block, 128 blocks. Lane handles 4 cols per step
// (uint2 = 4 halves); x shared reads are lane-stride 16B -> conflict-free.
__global__ void __launch_bounds__(256) k_rich_h(const float* __restrict__ xin,
                                                float* __restrict__ xout,
                                                const float* __restrict__ alphap) {
    __shared__ float sx[3 * NN];                       // 48 KB
    const float4* xin4 = (const float4*)xin;
    for (int idx = threadIdx.x; idx < (3 * NN) / 4; idx += 256)
        ((float4*)sx)[idx] = xin4[idx];
    __syncthreads();

    int warp = threadIdx.x >> 5, lane = threadIdx.x & 31;
    int r0 = (blockIdx.x << 5) + (warp << 2);
    const uint2* L0 = (const uint2*)(g_Lh + (size_t)r0 * NN);
    const uint2* L1 = (const uint2*)(g_Lh + (size_t)(r0 + 1) * NN);
    const uint2* L2 = (const uint2*)(g_Lh + (size_t)(r0 + 2) * NN);
    const uint2* L3 = (const uint2*)(g_Lh + (size_t)(r0 + 3) * NN);

    float a00 = 0.f, a01 = 0.f, a02 = 0.f;
    float a10 = 0.f, a11 = 0.f, a12 = 0.f;
    float a20 = 0.f, a21 = 0.f, a22 = 0.f;
    float a30 = 0.f, a31 = 0.f, a32 = 0.f;

    #pragma unroll 4
    for (int t = 0; t < 32; ++t) {
        int j = lane + (t << 5);                       // uint2 index; cols 4j..4j+3
        uint2 u0 = L0[j], u1 = L1[j], u2 = L2[j], u3 = L3[j];
        int b = j << 2;
        float4 x0 = *(const float4*)(sx + b);
        float4 x1 = *(const float4*)(sx + NN + b);
        float4 x2 = *(const float4*)(sx + 2 * NN + b);

        float2 p, q;
        p = __half22float2(*(const __half2*)&u0.x);
        q = __half22float2(*(const __half2*)&u0.y);
        a00 += p.x * x0.x + p.y * x0.y + q.x * x0.z + q.y * x0.w;
        a01 += p.x * x1.x + p.y * x1.y + q.x * x1.z + q.y * x1.w;
        a02 += p.x * x2.x + p.y * x2.y + q.x * x2.z + q.y * x2.w;

        p = __half22float2(*(const __half2*)&u1.x);
        q = __half22float2(*(const __half2*)&u1.y);
        a10 += p.x * x0.x + p.y * x0.y + q.x * x0.z + q.y * x0.w;
        a11 += p.x * x1.x + p.y * x1.y + q.x * x1.z + q.y * x1.w;
        a12 += p.x * x2.x + p.y * x2.y + q.x * x2.z + q.y * x2.w;

        p = __half22float2(*(const __half2*)&u2.x);
        q = __half22float2(*(const __half2*)&u2.y);
        a20 += p.x * x0.x + p.y * x0.y + q.x * x0.z + q.y * x0.w;
        a21 += p.x * x1.x + p.y * x1.y + q.x * x1.z + q.y * x1.w;
        a22 += p.x * x2.x + p.y * x2.y + q.x * x2.z + q.y * x2.w;

        p = __half22float2(*(const __half2*)&u3.x);
        q = __half22float2(*(const __half2*)&u3.y);
        a30 += p.x * x0.x + p.y * x0.y + q.x * x0.z + q.y * x0.w;
        a31 += p.x * x1.x + p.y * x1.y + q.x * x1.z + q.y * x1.w;
        a32 += p.x * x2.x + p.y * x2.y + q.x * x2.z + q.y * x2.w;
    }

    #pragma unroll
    for (int o = 16; o; o >>= 1) {
        a00 += __shfl_down_sync(0xffffffffu, a00, o);
        a01 += __shfl_down_sync(0xffffffffu, a01, o);
        a02 += __shfl_down_sync(0xffffffffu, a02, o);
        a10 += __shfl_down_sync(0xffffffffu, a10, o);
        a11 += __shfl_down_sync(0xffffffffu, a11, o);
        a12 += __shfl_down_sync(0xffffffffu, a12, o);
        a20 += __shfl_down_sync(0xffffffffu, a20, o);
        a21 += __shfl_down_sync(0xffffffffu, a21, o);
        a22 += __shfl_down_sync(0xffffffffu, a22, o);
        a30 += __shfl_down_sync(0xffffffffu, a30, o);
        a31 += __shfl_down_sync(0xffffffffu, a31, o);
        a32 += __shfl_down_sync(0xffffffffu, a32, o);
    }
    if (lane == 0) {
        float al = *alphap;
        xout[r0]              = g_rhs[r0]              + al * a00;
        xout[NN + r0]         = g_rhs[NN + r0]         + al * a01;
        xout[2 * NN + r0]     = g_rhs[2 * NN + r0]     + al * a02;
        xout[r0 + 1]          = g_rhs[r0 + 1]          + al * a10;
        xout[NN + r0 + 1]     = g_rhs[NN + r0 + 1]     + al * a11;
        xout[2 * NN + r0 + 1] = g_rhs[2 * NN + r0 + 1] + al * a12;
        xout[r0 + 2]          = g_rhs[r0 + 2]          + al * a20;
        xout[NN + r0 + 2]     = g_rhs[NN + r0 + 2]     + al * a21;
        xout[2 * NN + r0 + 2] = g_rhs[2 * NN + r0 + 2] + al * a22;
        xout[r0 + 3]          = g_rhs[r0 + 3]          + al * a30;
        xout[NN + r0 + 3]     = g_rhs[NN + r0 + 3]     + al * a31;
        xout[2 * NN + r0 + 3] = g_rhs[2 * NN + r0 + 3] + al * a32;
    }
}

// fp32 Richardson step (polish): 4 rows/warp, as in R2.
__global__ void __launch_bounds__(128) k_rich(const float* __restrict__ L,
                                              const float* __restrict__ xin,
                                              float* __restrict__ xout,
                                              const float* __restrict__ alphap) {
    __shared__ float sx[3 * NN];                       // 48 KB
    const float4* xin4 = (const float4*)xin;
    for (int idx = threadIdx.x; idx < (3 * NN) / 4; idx += 128)
        ((float4*)sx)[idx] = xin4[idx];
    __syncthreads();

    int warp = threadIdx.x >> 5, lane = threadIdx.x & 31;
    int r0 = (blockIdx.x << 4) + (warp << 2);          // 256 blocks * 16 rows
    const float4* L0 = (const float4*)(L + (size_t)r0 * NN);
    const float4* L1 = (const float4*)(L + (size_t)(r0 + 1) * NN);
    const float4* L2 = (const float4*)(L + (size_t)(r0 + 2) * NN);
    const float4* L3 = (const float4*)(L + (size_t)(r0 + 3) * NN);

    float a00 = 0.f, a01 = 0.f, a02 = 0.f;
    float a10 = 0.f, a11 = 0.f, a12 = 0.f;
    float a20 = 0.f, a21 = 0.f, a22 = 0.f;
    float a30 = 0.f, a31 = 0.f, a32 = 0.f;

    #pragma unroll 2
    for (int t = 0; t < 32; ++t) {
        int j4 = lane + (t << 5);
        float4 l0 = L0[j4];
        float4 l1 = L1[j4];
        float4 l2 = L2[j4];
        float4 l3 = L3[j4];
        int b = j4 << 2;
        float4 x0 = *(const float4*)(sx + b);
        float4 x1 = *(const float4*)(sx + NN + b);
        float4 x2 = *(const float4*)(sx + 2 * NN + b);

        a00 += l0.x * x0.x + l0.y * x0.y + l0.z * x0.z + l0.w * x0.w;
        a01 += l0.x * x1.x + l0.y * x1.y + l0.z * x1.z + l0.w * x1.w;
        a02 += l0.x * x2.x + l0.y * x2.y + l0.z * x2.z + l0.w * x2.w;

        a10 += l1.x * x0.x + l1.y * x0.y + l1.z * x0.z + l1.w * x0.w;
        a11 += l1.x * x1.x + l1.y * x1.y + l1.z * x1.z + l1.w * x1.w;
        a12 += l1.x * x2.x + l1.y * x2.y + l1.z * x2.z + l1.w * x2.w;

        a20 += l2.x * x0.x + l2.y * x0.y + l2.z * x0.z + l2.w * x0.w;
        a21 += l2.x * x1.x + l2.y * x1.y + l2.z * x1.z + l2.w * x1.w;
        a22 += l2.x * x2.x + l2.y * x2.y + l2.z * x2.z + l2.w * x2.w;

        a30 += l3.x * x0.x + l3.y * x0.y + l3.z * x0.z + l3.w * x0.w;
        a31 += l3.x * x1.x + l3.y * x1.y + l3.z * x1.z + l3.w * x1.w;
        a32 += l3.x * x2.x + l3.y * x2.y + l3.z * x2.z + l3.w * x2.w;
    }

    #pragma unroll
    for (int o = 16; o; o >>= 1) {
        a00 += __shfl_down_sync(0xffffffffu, a00, o);
        a01 += __shfl_down_sync(0xffffffffu, a01, o);
        a02 += __shfl_down_sync(0xffffffffu, a02, o);
        a10 += __shfl_down_sync(0xffffffffu, a10, o);
        a11 += __shfl_down_sync(0xffffffffu, a11, o);
        a12 += __shfl_down_sync(0xffffffffu, a12, o);
        a20 += __shfl_down_sync(0xffffffffu, a20, o);
        a21 += __shfl_down_sync(0xffffffffu, a21, o);
        a22 += __shfl_down_sync(0xffffffffu, a22, o);
        a30 += __shfl_down_sync(0xffffffffu, a30, o);
        a31 += __shfl_down_sync(0xffffffffu, a31, o);
        a32 += __shfl_down_sync(0xffffffffu, a32, o);
    }
    if (lane == 0) {
        float al = *alphap;
        xout[r0]              = g_rhs[r0]              + al * a00;
        xout[NN + r0]         = g_rhs[NN + r0]         + al * a01;
        xout[2 * NN + r0]     = g_rhs[2 * NN + r0]     + al * a02;
        xout[r0 + 1]          = g_rhs[r0 + 1]          + al * a10;
        xout[NN + r0 + 1]     = g_rhs[NN + r0 + 1]     + al * a11;
        xout[2 * NN + r0 + 1] = g_rhs[2 * NN + r0 + 1] + al * a12;
        xout[r0 + 2]          = g_rhs[r0 + 2]          + al * a20;
        xout[NN + r0 + 2]     = g_rhs[NN + r0 + 2]     + al * a21;
        xout[2 * NN + r0 + 2] = g_rhs[2 * NN + r0 + 2] + al * a22;
        xout[r0 + 3]          = g_rhs[r0 + 3]          + al * a30;
        xout[NN + r0 + 3]     = g_rhs[NN + r0 + 3]     + al * a31;
        xout[2 * NN + r0 + 3] = g_rhs[2 * NN + r0 + 3] + al * a32;
    }
}

// ---------------- GCN layers -------------------------------------------------
// fused featfin + linear1: feat = [dv, (1-a)*sol0, (1-a)*sol1, (1-a)*sol2]
__global__ void k_lin1(const float* __restrict__ dv, const float* __restrict__ xfin,
                       const float* __restrict__ alphap,
                       const float* __restrict__ w1, const float* __restrict__ b1) {
    int id = blockIdx.x * blockDim.x + threadIdx.x;    // NN*F threads
    if (id < NN * F) {
        int i = id >> 7, f = id & 127;
        float s = 1.0f - *alphap;
        float c0 = dv[i];
        float c1 = s * xfin[i];
        float c2 = s * xfin[NN + i];
        float c3 = s * xfin[2 * NN + i];
        float acc = b1[f] + c0 * w1[f] + c1 * w1[F + f] + c2 * w1[2 * F + f] + c3 * w1[3 * F + f];
        g_h1[id] = acc;
    }
}

__global__ void __launch_bounds__(128) k_aggr(const float* __restrict__ hin,
                                              float* __restrict__ hout, int relu) {
    int i = blockIdx.x;
    int f = threadIdx.x;
    float d = g_dis[i];
    float acc = d * d * hin[i * F + f];                // self loop
    int e = g_off[i], end = g_off[i + 1];
    for (; e + 4 <= end; e += 4) {
        int   s0 = g_esrc[e],     s1 = g_esrc[e + 1], s2 = g_esrc[e + 2], s3 = g_esrc[e + 3];
        float n0 = g_enorm[e],    n1 = g_enorm[e + 1], n2 = g_enorm[e + 2], n3 = g_enorm[e + 3];
        acc += n0 * hin[s0 * F + f] + n1 * hin[s1 * F + f]
             + n2 * hin[s2 * F + f] + n3 * hin[s3 * F + f];
    }
    for (; e < end; ++e)
        acc += g_enorm[e] * hin[g_esrc[e] * F + f];
    if (relu) acc = fmaxf(acc, 0.0f);
    hout[i * F + f] = acc;
}

__global__ void k_lin2(const float* __restrict__ hin, float* __restrict__ hout,
                       const float* __restrict__ w2, const float* __restrict__ b2) {
    int id = blockIdx.x * blockDim.x + threadIdx.x;
    if (id < NN * F) {
        int i = id >> 7, f = id & 127;
        const float* hr = hin + i * F;
        float acc = b2[f];
        #pragma unroll 8
        for (int g = 0; g < F; ++g)
            acc += hr[g] * w2[g * F + f];
        hout[id] = acc;
    }
}

__global__ void k_final(const float* __restrict__ hin, const float* __restrict__ wf,
                        const float* __restrict__ bf, float* __restrict__ out) {
    int gid = blockIdx.x * blockDim.x + threadIdx.x;
    int node = gid >> 5, lane = gid & 31;
    if (node < NN) {
        float a0 = 0.f, a1 = 0.f;
        #pragma unroll
        for (int f = lane; f < F; f += 32) {
            float h = hin[node * F + f];
            a0 += h * wf[2 * f];
            a1 += h * wf[2 * f + 1];
        }
        #pragma unroll
        for (int o = 16; o; o >>= 1) {
            a0 += __shfl_down_sync(0xffffffffu, a0, o);
            a1 += __shfl_down_sync(0xffffffffu, a1, o);
        }
        if (lane == 0) {
            out[2 * node]     = a0 + bf[0];
            out[2 * node + 1] = a1 + bf[1];
        }
    }
}

// ---------------- driver -----------------------------------------------------
extern "C" void kernel_launch(void* const* d_in, const int* in_sizes, int n_in,
                              void* d_out, int out_size) {
    const float* alpha = (const float*)d_in[0];
    const float* L     = (const float*)d_in[1];
    const float* thr   = (const float*)d_in[2];
    const float* dv    = (const float*)d_in[3];
    const int*   ei    = (const int*)  d_in[4];
    const float* w1    = (const float*)d_in[5];
    const float* b1    = (const float*)d_in[6];
    const float* w2    = (const float*)d_in[7];
    const float* b2    = (const float*)d_in[8];
    const float* wf    = (const float*)d_in[9];
    const float* bf    = (const float*)d_in[10];
    float* out = (float*)d_out;
    int E = in_sizes[4] / 2;

    float *pa, *pb, *h1, *h2;
    cudaGetSymbolAddress((void**)&pa, g_xA);
    cudaGetSymbolAddress((void**)&pb, g_xB);
    cudaGetSymbolAddress((void**)&h1, g_h1);
    cudaGetSymbolAddress((void**)&h2, g_h2);

    k_init<<<NN / 256, 256>>>();
    k_edges<<<(E + 255) / 256, 256>>>(ei, E);
    k_dis<<<NN / 256, 256>>>();
    k_scan<<<1, 1024>>>();
    k_fill<<<(E + 255) / 256, 256>>>(ei, E);
    k_rhs<<<NN / 256, 256>>>(dv, thr);
    k_cvt<<<(NN * NN / 4) / 256, 256>>>(L);

    float* cur = pa;
    float* nxt = pb;
    for (int k = 0; k < K_H; ++k) {
        k_rich_h<<<NN / 32, 256>>>(cur, nxt, alpha);
        float* t = cur; cur = nxt; nxt = t;
    }
    for (int k = 0; k < K_F32; ++k) {
        k_rich<<<NN / 16, 128>>>(L, cur, nxt, alpha);
        float* t = cur; cur = nxt; nxt = t;
    }

    k_lin1<<<(NN * F) / 256, 256>>>(dv, cur, alpha, w1, b1);
    k_aggr<<<NN, 128>>>(h1, h2, 1);
    k_lin2<<<(NN * F) / 256, 256>>>(h2, h1, w2, b2);
    k_aggr<<<NN, 128>>>(h1, h2, 0);
    k_final<<<(NN * 32) / 256, 256>>>(h2, wf, bf, out);
}

// round 4
// speedup vs baseline: 2.1638x; 1.0078x over previous
#include <cuda_runtime.h>
#include <cuda_fp16.h>
#include <math.h>

#define NN 4096            // nodes
#define EE 131072          // edges
#define F  128             // hidden feature width
#define K_H 12             // fp16 Richardson iterations (even -> result lands in g_xA)
#define NB 128             // mega-kernel blocks (all co-resident: <=1/SM of 148)
#define NT 256
#define GTOT (NB * NT)

// ---------------- scratch (static device globals; no allocation) ------------
__device__ int    g_deg[NN];
__device__ int    g_cnt[NN];
__device__ int    g_cur[NN];
__device__ int    g_off[NN + 1];
__device__ float  g_dis[NN];           // deg^{-1/2}
__device__ int    g_esrc[EE];
__device__ float  g_enorm[EE];
__device__ float  g_rhs[3 * NN];       // SoA: 3 columns of 4096
__device__ float  g_xA[3 * NN];
__device__ float  g_xB[3 * NN];
__device__ float  g_h1[NN * F];
__device__ float  g_h2[NN * F];
__device__ __half g_Lh[(size_t)NN * NN];   // fp16 copy of laplacian (32 MB)

// grid barrier state (zero-init; count self-resets, gen monotonic across replays)
__device__ int g_barcnt;
__device__ int g_bargen;

__device__ __forceinline__ void gbar() {
    __threadfence();
    __syncthreads();
    if (threadIdx.x == 0) {
        int gen = *(volatile int*)&g_bargen;
        if (atomicAdd(&g_barcnt, 1) == NB - 1) {
            g_barcnt = 0;
            __threadfence();
            *(volatile int*)&g_bargen = gen + 1;
        } else {
            while (*(volatile int*)&g_bargen == gen) __nanosleep(64);
        }
        __threadfence();
    }
    __syncthreads();
}

// ---------------- mega kernel: preproc + cvt + 12 fp16 iters + lin1 ----------
__global__ void __launch_bounds__(NT) k_mega(const float* __restrict__ L,
                                             const int* __restrict__ ei, int E,
                                             const float* __restrict__ dv,
                                             const float* __restrict__ thrp,
                                             const float* __restrict__ alphap,
                                             const float* __restrict__ w1,
                                             const float* __restrict__ b1) {
    __shared__ float sx[3 * NN];                       // 48 KB (reused as scan scratch)
    const int g = blockIdx.x * NT + threadIdx.x;

    // ---- P0: init counters + rhs + x0 ----
    for (int i = g; i < NN; i += GTOT) {
        g_deg[i] = 1; g_cnt[i] = 0; g_cur[i] = 0;      // deg=1: self loop
        float t = *thrp;
        float d = dv[i];
        float r0 = d, r1 = fmaxf(d, t), r2 = fminf(d, t);
        g_rhs[i] = r0;  g_rhs[NN + i] = r1;  g_rhs[2 * NN + i] = r2;
        g_xA[i]  = r0;  g_xA[NN + i]  = r1;  g_xA[2 * NN + i]  = r2;
    }
    gbar();

    // ---- P1: degree/count atomics + L fp32->fp16 convert ----
    for (int e = g; e < E; e += GTOT) {
        int r = ei[e];
        int c = ei[E + e];
        atomicAdd(&g_deg[r], 1);
        atomicAdd(&g_cnt[c], 1);
    }
    {
        const float4* L4 = (const float4*)L;
        uint2* O = (uint2*)g_Lh;
        for (int idx = g; idx < NN * NN / 4; idx += GTOT) {
            float4 v = L4[idx];
            __half2 h01 = __floats2half2_rn(v.x, v.y);
            __half2 h23 = __floats2half2_rn(v.z, v.w);
            uint2 o;
            o.x = *(const unsigned int*)&h01;
            o.y = *(const unsigned int*)&h23;
            O[idx] = o;
        }
    }
    gbar();

    // ---- P2: block 0 scans g_cnt -> g_off; other blocks compute deg^-1/2 ----
    if (blockIdx.x == 0) {
        int t = threadIdx.x;
        int lane = t & 31, wid = t >> 5;
        int* wsum = (int*)sx;
        int vals[16]; int s = 0;
        int base = t << 4;
        #pragma unroll
        for (int j = 0; j < 16; ++j) { vals[j] = g_cnt[base + j]; s += vals[j]; }
        int v = s;
        #pragma unroll
        for (int o = 1; o < 32; o <<= 1) {
            int u = __shfl_up_sync(0xffffffffu, v, o);
            if (lane >= o) v += u;
        }
        if (lane == 31) wsum[wid] = v;
        __syncthreads();
        if (wid == 0) {
            int w = (lane < 8) ? wsum[lane] : 0;
            #pragma unroll
            for (int o = 1; o < 8; o <<= 1) {
                int u = __shfl_up_sync(0xffffffffu, w, o);
                if (lane >= o) w += u;
            }
            if (lane < 8) wsum[lane] = w;
        }
        __syncthreads();
        int run = v - s + (wid ? wsum[wid - 1] : 0);
        #pragma unroll
        for (int j = 0; j < 16; ++j) { g_off[base + j] = run; run += vals[j]; }
        if (t == NT - 1) g_off[NN] = run;
        __syncthreads();
    } else {
        for (int i = (blockIdx.x - 1) * NT + threadIdx.x; i < NN; i += (NB - 1) * NT)
            g_dis[i] = rsqrtf((float)g_deg[i]);
    }
    gbar();

    // ---- P3: CSR fill (not needed by the solve; no barrier after) ----
    for (int e = g; e < E; e += GTOT) {
        int r = ei[e];
        int c = ei[E + e];
        int p = g_off[c] + atomicAdd(&g_cur[c], 1);
        g_esrc[p]  = r;
        g_enorm[p] = g_dis[r] * g_dis[c];
    }

    // ---- Richardson iterations on fp16 L (fp32 accum), 1 grid barrier each ----
    const int warp = threadIdx.x >> 5, lane = threadIdx.x & 31;
    const int r0 = (blockIdx.x << 5) + (warp << 2);
    const float al = *alphap;

    for (int k = 0; k < K_H; ++k) {
        const float* xin = (k & 1) ? g_xB : g_xA;
        float*       xout = (k & 1) ? g_xA : g_xB;

        const float4* xin4 = (const float4*)xin;
        for (int idx = threadIdx.x; idx < (3 * NN) / 4; idx += NT)
            ((float4*)sx)[idx] = xin4[idx];
        __syncthreads();

        const uint2* L0 = (const uint2*)(g_Lh + (size_t)r0 * NN);
        const uint2* L1 = (const uint2*)(g_Lh + (size_t)(r0 + 1) * NN);
        const uint2* L2 = (const uint2*)(g_Lh + (size_t)(r0 + 2) * NN);
        const uint2* L3 = (const uint2*)(g_Lh + (size_t)(r0 + 3) * NN);

        float a00 = 0.f, a01 = 0.f, a02 = 0.f;
        float a10 = 0.f, a11 = 0.f, a12 = 0.f;
        float a20 = 0.f, a21 = 0.f, a22 = 0.f;
        float a30 = 0.f, a31 = 0.f, a32 = 0.f;

        #pragma unroll 4
        for (int t = 0; t < 32; ++t) {
            int j = lane + (t << 5);                   // uint2 index; cols 4j..4j+3
            uint2 u0 = L0[j], u1 = L1[j], u2 = L2[j], u3 = L3[j];
            int b = j << 2;
            float4 x0 = *(const float4*)(sx + b);
            float4 x1 = *(const float4*)(sx + NN + b);
            float4 x2 = *(const float4*)(sx + 2 * NN + b);

            float2 p, q;
            p = __half22float2(*(const __half2*)&u0.x);
            q = __half22float2(*(const __half2*)&u0.y);
            a00 += p.x * x0.x + p.y * x0.y + q.x * x0.z + q.y * x0.w;
            a01 += p.x * x1.x + p.y * x1.y + q.x * x1.z + q.y * x1.w;
            a02 += p.x * x2.x + p.y * x2.y + q.x * x2.z + q.y * x2.w;

            p = __half22float2(*(const __half2*)&u1.x);
            q = __half22float2(*(const __half2*)&u1.y);
            a10 += p.x * x0.x + p.y * x0.y + q.x * x0.z + q.y * x0.w;
            a11 += p.x * x1.x + p.y * x1.y + q.x * x1.z + q.y * x1.w;
            a12 += p.x * x2.x + p.y * x2.y + q.x * x2.z + q.y * x2.w;

            p = __half22float2(*(const __half2*)&u2.x);
            q = __half22float2(*(const __half2*)&u2.y);
            a20 += p.x * x0.x + p.y * x0.y + q.x * x0.z + q.y * x0.w;
            a21 += p.x * x1.x + p.y * x1.y + q.x * x1.z + q.y * x1.w;
            a22 += p.x * x2.x + p.y * x2.y + q.x * x2.z + q.y * x2.w;

            p = __half22float2(*(const __half2*)&u3.x);
            q = __half22float2(*(const __half2*)&u3.y);
            a30 += p.x * x0.x + p.y * x0.y + q.x * x0.z + q.y * x0.w;
            a31 += p.x * x1.x + p.y * x1.y + q.x * x1.z + q.y * x1.w;
            a32 += p.x * x2.x + p.y * x2.y + q.x * x2.z + q.y * x2.w;
        }

        #pragma unroll
        for (int o = 16; o; o >>= 1) {
            a00 += __shfl_down_sync(0xffffffffu, a00, o);
            a01 += __shfl_down_sync(0xffffffffu, a01, o);
            a02 += __shfl_down_sync(0xffffffffu, a02, o);
            a10 += __shfl_down_sync(0xffffffffu, a10, o);
            a11 += __shfl_down_sync(0xffffffffu, a11, o);
            a12 += __shfl_down_sync(0xffffffffu, a12, o);
            a20 += __shfl_down_sync(0xffffffffu, a20, o);
            a21 += __shfl_down_sync(0xffffffffu, a21, o);
            a22 += __shfl_down_sync(0xffffffffu, a22, o);
            a30 += __shfl_down_sync(0xffffffffu, a30, o);
            a31 += __shfl_down_sync(0xffffffffu, a31, o);
            a32 += __shfl_down_sync(0xffffffffu, a32, o);
        }
        if (lane == 0) {
            xout[r0]              = g_rhs[r0]              + al * a00;
            xout[NN + r0]         = g_rhs[NN + r0]         + al * a01;
            xout[2 * NN + r0]     = g_rhs[2 * NN + r0]     + al * a02;
            xout[r0 + 1]          = g_rhs[r0 + 1]          + al * a10;
            xout[NN + r0 + 1]     = g_rhs[NN + r0 + 1]     + al * a11;
            xout[2 * NN + r0 + 1] = g_rhs[2 * NN + r0 + 1] + al * a12;
            xout[r0 + 2]          = g_rhs[r0 + 2]          + al * a20;
            xout[NN + r0 + 2]     = g_rhs[NN + r0 + 2]     + al * a21;
            xout[2 * NN + r0 + 2] = g_rhs[2 * NN + r0 + 2] + al * a22;
            xout[r0 + 3]          = g_rhs[r0 + 3]          + al * a30;
            xout[NN + r0 + 3]     = g_rhs[NN + r0 + 3]     + al * a31;
            xout[2 * NN + r0 + 3] = g_rhs[2 * NN + r0 + 3] + al * a32;
        }
        gbar();
    }

    // ---- P_final: fused featfin + linear1 (final x lives in g_xA; K_H even) ----
    {
        float s = 1.0f - al;
        for (int id = g; id < NN * F; id += GTOT) {
            int i = id >> 7, f = id & 127;
            float c0 = dv[i];
            float c1 = s * g_xA[i];
            float c2 = s * g_xA[NN + i];
            float c3 = s * g_xA[2 * NN + i];
            g_h1[id] = b1[f] + c0 * w1[f] + c1 * w1[F + f]
                             + c2 * w1[2 * F + f] + c3 * w1[3 * F + f];
        }
    }
}

// ---------------- GCN tail ---------------------------------------------------
__global__ void __launch_bounds__(128) k_aggr1(const float* __restrict__ hin,
                                               float* __restrict__ hout) {
    int i = blockIdx.x;
    int f = threadIdx.x;
    float d = g_dis[i];
    float acc = d * d * hin[i * F + f];                // self loop
    int e = g_off[i], end = g_off[i + 1];
    for (; e + 4 <= end; e += 4) {
        int   s0 = g_esrc[e],  s1 = g_esrc[e + 1], s2 = g_esrc[e + 2], s3 = g_esrc[e + 3];
        float n0 = g_enorm[e], n1 = g_enorm[e + 1], n2 = g_enorm[e + 2], n3 = g_enorm[e + 3];
        acc += n0 * hin[s0 * F + f] + n1 * hin[s1 * F + f]
             + n2 * hin[s2 * F + f] + n3 * hin[s3 * F + f];
    }
    for (; e < end; ++e)
        acc += g_enorm[e] * hin[g_esrc[e] * F + f];
    hout[i * F + f] = fmaxf(acc, 0.0f);                // relu
}

__global__ void k_lin2(const float* __restrict__ hin, float* __restrict__ hout,
                       const float* __restrict__ w2, const float* __restrict__ b2) {
    int id = blockIdx.x * blockDim.x + threadIdx.x;
    if (id < NN * F) {
        int i = id >> 7, f = id & 127;
        const float* hr = hin + i * F;
        float acc = b2[f];
        #pragma unroll 8
        for (int gg = 0; gg < F; ++gg)
            acc += hr[gg] * w2[gg * F + f];
        hout[id] = acc;
    }
}

// aggregation (no relu) + final 128->2 projection, fused per node block
__global__ void __launch_bounds__(128) k_aggr2f(const float* __restrict__ hin,
                                                const float* __restrict__ wf,
                                                const float* __restrict__ bf,
                                                float* __restrict__ out) {
    __shared__ float sacc[F];
    int i = blockIdx.x;
    int f = threadIdx.x;
    float d = g_dis[i];
    float acc = d * d * hin[i * F + f];                // self loop
    int e = g_off[i], end = g_off[i + 1];
    for (; e + 4 <= end; e += 4) {
        int   s0 = g_esrc[e],  s1 = g_esrc[e + 1], s2 = g_esrc[e + 2], s3 = g_esrc[e + 3];
        float n0 = g_enorm[e], n1 = g_enorm[e + 1], n2 = g_enorm[e + 2], n3 = g_enorm[e + 3];
        acc += n0 * hin[s0 * F + f] + n1 * hin[s1 * F + f]
             + n2 * hin[s2 * F + f] + n3 * hin[s3 * F + f];
    }
    for (; e < end; ++e)
        acc += g_enorm[e] * hin[g_esrc[e] * F + f];
    sacc[f] = acc;
    __syncthreads();

    int warp = f >> 5, lane = f & 31;
    if (warp < 2) {                                    // warp w computes output col w
        float a = 0.f;
        #pragma unroll
        for (int b = 0; b < 4; ++b) {
            int ff = lane + b * 32;
            a += sacc[ff] * wf[2 * ff + warp];
        }
        #pragma unroll
        for (int o = 16; o; o >>= 1)
            a += __shfl_down_sync(0xffffffffu, a, o);
        if (lane == 0)
            out[2 * i + warp] = a + bf[warp];
    }
}

// ---------------- driver -----------------------------------------------------
extern "C" void kernel_launch(void* const* d_in, const int* in_sizes, int n_in,
                              void* d_out, int out_size) {
    const float* alpha = (const float*)d_in[0];
    const float* L     = (const float*)d_in[1];
    const float* thr   = (const float*)d_in[2];
    const float* dv    = (const float*)d_in[3];
    const int*   ei    = (const int*)  d_in[4];
    const float* w1    = (const float*)d_in[5];
    const float* b1    = (const float*)d_in[6];
    const float* w2    = (const float*)d_in[7];
    const float* b2    = (const float*)d_in[8];
    const float* wf    = (const float*)d_in[9];
    const float* bf    = (const float*)d_in[10];
    float* out = (float*)d_out;
    int E = in_sizes[4] / 2;

    float *h1, *h2;
    cudaGetSymbolAddress((void**)&h1, g_h1);
    cudaGetSymbolAddress((void**)&h2, g_h2);

    k_mega<<<NB, NT>>>(L, ei, E, dv, thr, alpha, w1, b1);
    k_aggr1<<<NN, 128>>>(h1, h2);
    k_lin2<<<(NN * F) / 256, 256>>>(h2, h1, w2, b2);
    k_aggr2f<<<NN, 128>>>(h1, wf, bf, out);
}

// round 9
// speedup vs baseline: 2.2264x; 1.0290x over previous
#include <cuda_runtime.h>
#include <cuda_bf16.h>
#include <math.h>

#define NN 4096            // nodes
#define EE 131072          // edges
#define F  128             // hidden feature width
#define K_TOT 12           // total Richardson iterations (iter0 fused with cvt)

// ---------------- scratch (static device globals; no allocation) ------------
__device__ int          g_deg[NN];
__device__ int          g_cnt[NN];
__device__ int          g_cur[NN];
__device__ int          g_off[NN + 1];
__device__ float        g_dis[NN];     // deg^{-1/2}
__device__ int          g_esrc[EE];
__device__ float        g_enorm[EE];
__device__ float        g_rhs[3 * NN]; // SoA: 3 columns of 4096
__device__ float        g_xA[3 * NN];
__device__ float        g_xB[3 * NN];
__device__ float        g_h1[NN * F];
__device__ float        g_h2[NN * F];
__device__ unsigned int g_Lb[(size_t)NN * NN / 2];  // bf16 copy of L, 2 elems/u32 (32 MB)

// ---------------- preprocessing ---------------------------------------------
__global__ void k_init() {
    int i = blockIdx.x * blockDim.x + threadIdx.x;
    if (i < NN) { g_deg[i] = 1; g_cnt[i] = 0; g_cur[i] = 0; }   // deg=1: self loop
}

__global__ void k_edges(const int* __restrict__ ei, int E) {
    int e = blockIdx.x * blockDim.x + threadIdx.x;
    if (e < E) {
        int r = ei[e];
        int c = ei[E + e];
        atomicAdd(&g_deg[r], 1);
        atomicAdd(&g_cnt[c], 1);
    }
}

__global__ void k_dis() {
    int i = blockIdx.x * blockDim.x + threadIdx.x;
    if (i < NN) g_dis[i] = rsqrtf((float)g_deg[i]);
}

// single-block exclusive scan of g_cnt[4096] -> g_off[4097]
__global__ void k_scan() {
    __shared__ int wsum[32];
    int t = threadIdx.x;                 // 1024 threads, 4 elems each
    int lane = t & 31, wid = t >> 5;
    int c0 = g_cnt[4 * t], c1 = g_cnt[4 * t + 1], c2 = g_cnt[4 * t + 2], c3 = g_cnt[4 * t + 3];
    int local = c0 + c1 + c2 + c3;
    int v = local;
    #pragma unroll
    for (int o = 1; o < 32; o <<= 1) {
        int u = __shfl_up_sync(0xffffffffu, v, o);
        if (lane >= o) v += u;
    }
    if (lane == 31) wsum[wid] = v;
    __syncthreads();
    if (wid == 0) {
        int w = wsum[lane];
        #pragma unroll
        for (int o = 1; o < 32; o <<= 1) {
            int u = __shfl_up_sync(0xffffffffu, w, o);
            if (lane >= o) w += u;
        }
        wsum[lane] = w;
    }
    __syncthreads();
    int base = v - local + (wid ? wsum[wid - 1] : 0);
    g_off[4 * t]     = base;
    g_off[4 * t + 1] = base + c0;
    g_off[4 * t + 2] = base + c0 + c1;
    g_off[4 * t + 3] = base + c0 + c1 + c2;
    if (t == 1023) g_off[NN] = base + local;
}

__global__ void k_fill(const int* __restrict__ ei, int E) {
    int e = blockIdx.x * blockDim.x + threadIdx.x;
    if (e < E) {
        int r = ei[e];
        int c = ei[E + e];
        int p = g_off[c] + atomicAdd(&g_cur[c], 1);
        g_esrc[p]  = r;
        g_enorm[p] = g_dis[r] * g_dis[c];
    }
}

__global__ void k_rhs(const float* __restrict__ dv, const float* __restrict__ thrp) {
    int i = blockIdx.x * blockDim.x + threadIdx.x;
    if (i < NN) {
        float t = *thrp;
        float d = dv[i];
        float r0 = d, r1 = fmaxf(d, t), r2 = fminf(d, t);
        g_rhs[i] = r0;  g_rhs[NN + i] = r1;  g_rhs[2 * NN + i] = r2;
        g_xA[i]  = r0;  g_xA[NN + i]  = r1;  g_xA[2 * NN + i]  = r2;
    }
}

// ---------------- iteration 0 (fp32 L from DRAM) fused with bf16 convert -----
// 4 rows/warp, 4 warps/block, 256 blocks. Reads fp32 L once, writes g_Lb.
__global__ void __launch_bounds__(128) k_rich0(const float* __restrict__ L,
                                               const float* __restrict__ xin,
                                               float* __restrict__ xout,
                                               const float* __restrict__ alphap) {
    __shared__ float sx[3 * NN];                       // 48 KB
    const float4* xin4 = (const float4*)xin;
    for (int idx = threadIdx.x; idx < (3 * NN) / 4; idx += 128)
        ((float4*)sx)[idx] = xin4[idx];
    __syncthreads();

    int warp = threadIdx.x >> 5, lane = threadIdx.x & 31;
    int r0 = (blockIdx.x << 4) + (warp << 2);          // 256 blocks * 16 rows
    const float4* L0 = (const float4*)(L + (size_t)r0 * NN);
    const float4* L1 = (const float4*)(L + (size_t)(r0 + 1) * NN);
    const float4* L2 = (const float4*)(L + (size_t)(r0 + 2) * NN);
    const float4* L3 = (const float4*)(L + (size_t)(r0 + 3) * NN);
    uint2* B0 = (uint2*)(g_Lb + (size_t)r0 * (NN / 2));
    uint2* B1 = (uint2*)(g_Lb + (size_t)(r0 + 1) * (NN / 2));
    uint2* B2 = (uint2*)(g_Lb + (size_t)(r0 + 2) * (NN / 2));
    uint2* B3 = (uint2*)(g_Lb + (size_t)(r0 + 3) * (NN / 2));

    float a00 = 0.f, a01 = 0.f, a02 = 0.f;
    float a10 = 0.f, a11 = 0.f, a12 = 0.f;
    float a20 = 0.f, a21 = 0.f, a22 = 0.f;
    float a30 = 0.f, a31 = 0.f, a32 = 0.f;

    #pragma unroll 2
    for (int t = 0; t < 32; ++t) {
        int j4 = lane + (t << 5);
        float4 l0 = L0[j4];
        float4 l1 = L1[j4];
        float4 l2 = L2[j4];
        float4 l3 = L3[j4];
        int b = j4 << 2;
        float4 x0 = *(const float4*)(sx + b);
        float4 x1 = *(const float4*)(sx + NN + b);
        float4 x2 = *(const float4*)(sx + 2 * NN + b);

        // bf16 convert + store (round-to-nearest)
        {
            __nv_bfloat162 p0 = __floats2bfloat162_rn(l0.x, l0.y);
            __nv_bfloat162 q0 = __floats2bfloat162_rn(l0.z, l0.w);
            B0[j4] = make_uint2(*(unsigned int*)&p0, *(unsigned int*)&q0);
            __nv_bfloat162 p1 = __floats2bfloat162_rn(l1.x, l1.y);
            __nv_bfloat162 q1 = __floats2bfloat162_rn(l1.z, l1.w);
            B1[j4] = make_uint2(*(unsigned int*)&p1, *(unsigned int*)&q1);
            __nv_bfloat162 p2 = __floats2bfloat162_rn(l2.x, l2.y);
            __nv_bfloat162 q2 = __floats2bfloat162_rn(l2.z, l2.w);
            B2[j4] = make_uint2(*(unsigned int*)&p2, *(unsigned int*)&q2);
            __nv_bfloat162 p3 = __floats2bfloat162_rn(l3.x, l3.y);
            __nv_bfloat162 q3 = __floats2bfloat162_rn(l3.z, l3.w);
            B3[j4] = make_uint2(*(unsigned int*)&p3, *(unsigned int*)&q3);
        }

        a00 += l0.x * x0.x + l0.y * x0.y + l0.z * x0.z + l0.w * x0.w;
        a01 += l0.x * x1.x + l0.y * x1.y + l0.z * x1.z + l0.w * x1.w;
        a02 += l0.x * x2.x + l0.y * x2.y + l0.z * x2.z + l0.w * x2.w;

        a10 += l1.x * x0.x + l1.y * x0.y + l1.z * x0.z + l1.w * x0.w;
        a11 += l1.x * x1.x + l1.y * x1.y + l1.z * x1.z + l1.w * x1.w;
        a12 += l1.x * x2.x + l1.y * x2.y + l1.z * x2.z + l1.w * x2.w;

        a20 += l2.x * x0.x + l2.y * x0.y + l2.z * x0.z + l2.w * x0.w;
        a21 += l2.x * x1.x + l2.y * x1.y + l2.z * x1.z + l2.w * x1.w;
        a22 += l2.x * x2.x + l2.y * x2.y + l2.z * x2.z + l2.w * x2.w;

        a30 += l3.x * x0.x + l3.y * x0.y + l3.z * x0.z + l3.w * x0.w;
        a31 += l3.x * x1.x + l3.y * x1.y + l3.z * x1.z + l3.w * x1.w;
        a32 += l3.x * x2.x + l3.y * x2.y + l3.z * x2.z + l3.w * x2.w;
    }

    #pragma unroll
    for (int o = 16; o; o >>= 1) {
        a00 += __shfl_down_sync(0xffffffffu, a00, o);
        a01 += __shfl_down_sync(0xffffffffu, a01, o);
        a02 += __shfl_down_sync(0xffffffffu, a02, o);
        a10 += __shfl_down_sync(0xffffffffu, a10, o);
        a11 += __shfl_down_sync(0xffffffffu, a11, o);
        a12 += __shfl_down_sync(0xffffffffu, a12, o);
        a20 += __shfl_down_sync(0xffffffffu, a20, o);
        a21 += __shfl_down_sync(0xffffffffu, a21, o);
        a22 += __shfl_down_sync(0xffffffffu, a22, o);
        a30 += __shfl_down_sync(0xffffffffu, a30, o);
        a31 += __shfl_down_sync(0xffffffffu, a31, o);
        a32 += __shfl_down_sync(0xffffffffu, a32, o);
    }
    if (lane == 0) {
        float al = *alphap;
        xout[r0]              = g_rhs[r0]              + al * a00;
        xout[NN + r0]         = g_rhs[NN + r0]         + al * a01;
        xout[2 * NN + r0]     = g_rhs[2 * NN + r0]     + al * a02;
        xout[r0 + 1]          = g_rhs[r0 + 1]          + al * a10;
        xout[NN + r0 + 1]     = g_rhs[NN + r0 + 1]     + al * a11;
        xout[2 * NN + r0 + 1] = g_rhs[2 * NN + r0 + 1] + al * a12;
        xout[r0 + 2]          = g_rhs[r0 + 2]          + al * a20;
        xout[NN + r0 + 2]     = g_rhs[NN + r0 + 2]     + al * a21;
        xout[2 * NN + r0 + 2] = g_rhs[2 * NN + r0 + 2] + al * a22;
        xout[r0 + 3]          = g_rhs[r0 + 3]          + al * a30;
        xout[NN + r0 + 3]     = g_rhs[NN + r0 + 3]     + al * a31;
        xout[2 * NN + r0 + 3] = g_rhs[2 * NN + r0 + 3] + al * a32;
    }
}

// ---------------- bf16-L Richardson step -------------------------------------
// bf16 -> fp32 unpack is shift/and on the alu pipe: no F2F converts at all.
// 8 warps * 4 rows = 32 rows/block, 128 blocks.
__global__ void __launch_bounds__(256) k_richb(const float* __restrict__ xin,
                                               float* __restrict__ xout,
                                               const float* __restrict__ alphap) {
    __shared__ float sx[3 * NN];                       // 48 KB
    const float4* xin4 = (const float4*)xin;
    for (int idx = threadIdx.x; idx < (3 * NN) / 4; idx += 256)
        ((float4*)sx)[idx] = xin4[idx];
    __syncthreads();

    int warp = threadIdx.x >> 5, lane = threadIdx.x & 31;
    int r0 = (blockIdx.x << 5) + (warp << 2);
    const uint2* L0 = (const uint2*)(g_Lb + (size_t)r0 * (NN / 2));
    const uint2* L1 = (const uint2*)(g_Lb + (size_t)(r0 + 1) * (NN / 2));
    const uint2* L2 = (const uint2*)(g_Lb + (size_t)(r0 + 2) * (NN / 2));
    const uint2* L3 = (const uint2*)(g_Lb + (size_t)(r0 + 3) * (NN / 2));

    float a00 = 0.f, a01 = 0.f, a02 = 0.f;
    float a10 = 0.f, a11 = 0.f, a12 = 0.f;
    float a20 = 0.f, a21 = 0.f, a22 = 0.f;
    float a30 = 0.f, a31 = 0.f, a32 = 0.f;

    #pragma unroll 4
    for (int t = 0; t < 32; ++t) {
        int j = lane + (t << 5);                       // uint2 idx; cols 4j..4j+3
        uint2 u0 = L0[j], u1 = L1[j], u2 = L2[j], u3 = L3[j];
        int b = j << 2;
        float4 x0 = *(const float4*)(sx + b);
        float4 x1 = *(const float4*)(sx + NN + b);
        float4 x2 = *(const float4*)(sx + 2 * NN + b);

        float e0, e1, e2, e3;
        e0 = __uint_as_float(u0.x << 16);
        e1 = __uint_as_float(u0.x & 0xffff0000u);
        e2 = __uint_as_float(u0.y << 16);
        e3 = __uint_as_float(u0.y & 0xffff0000u);
        a00 += e0 * x0.x + e1 * x0.y + e2 * x0.z + e3 * x0.w;
        a01 += e0 * x1.x + e1 * x1.y + e2 * x1.z + e3 * x1.w;
        a02 += e0 * x2.x + e1 * x2.y + e2 * x2.z + e3 * x2.w;

        e0 = __uint_as_float(u1.x << 16);
        e1 = __uint_as_float(u1.x & 0xffff0000u);
        e2 = __uint_as_float(u1.y << 16);
        e3 = __uint_as_float(u1.y & 0xffff0000u);
        a10 += e0 * x0.x + e1 * x0.y + e2 * x0.z + e3 * x0.w;
        a11 += e0 * x1.x + e1 * x1.y + e2 * x1.z + e3 * x1.w;
        a12 += e0 * x2.x + e1 * x2.y + e2 * x2.z + e3 * x2.w;

        e0 = __uint_as_float(u2.x << 16);
        e1 = __uint_as_float(u2.x & 0xffff0000u);
        e2 = __uint_as_float(u2.y << 16);
        e3 = __uint_as_float(u2.y & 0xffff0000u);
        a20 += e0 * x0.x + e1 * x0.y + e2 * x0.z + e3 * x0.w;
        a21 += e0 * x1.x + e1 * x1.y + e2 * x1.z + e3 * x1.w;
        a22 += e0 * x2.x + e1 * x2.y + e2 * x2.z + e3 * x2.w;

        e0 = __uint_as_float(u3.x << 16);
        e1 = __uint_as_float(u3.x & 0xffff0000u);
        e2 = __uint_as_float(u3.y << 16);
        e3 = __uint_as_float(u3.y & 0xffff0000u);
        a30 += e0 * x0.x + e1 * x0.y + e2 * x0.z + e3 * x0.w;
        a31 += e0 * x1.x + e1 * x1.y + e2 * x1.z + e3 * x1.w;
        a32 += e0 * x2.x + e1 * x2.y + e2 * x2.z + e3 * x2.w;
    }

    #pragma unroll
    for (int o = 16; o; o >>= 1) {
        a00 += __shfl_down_sync(0xffffffffu, a00, o);
        a01 += __shfl_down_sync(0xffffffffu, a01, o);
        a02 += __shfl_down_sync(0xffffffffu, a02, o);
        a10 += __shfl_down_sync(0xffffffffu, a10, o);
        a11 += __shfl_down_sync(0xffffffffu, a11, o);
        a12 += __shfl_down_sync(0xffffffffu, a12, o);
        a20 += __shfl_down_sync(0xffffffffu, a20, o);
        a21 += __shfl_down_sync(0xffffffffu, a21, o);
        a22 += __shfl_down_sync(0xffffffffu, a22, o);
        a30 += __shfl_down_sync(0xffffffffu, a30, o);
        a31 += __shfl_down_sync(0xffffffffu, a31, o);
        a32 += __shfl_down_sync(0xffffffffu, a32, o);
    }
    if (lane == 0) {
        float al = *alphap;
        xout[r0]              = g_rhs[r0]              + al * a00;
        xout[NN + r0]         = g_rhs[NN + r0]         + al * a01;
        xout[2 * NN + r0]     = g_rhs[2 * NN + r0]     + al * a02;
        xout[r0 + 1]          = g_rhs[r0 + 1]          + al * a10;
        xout[NN + r0 + 1]     = g_rhs[NN + r0 + 1]     + al * a11;
        xout[2 * NN + r0 + 1] = g_rhs[2 * NN + r0 + 1] + al * a12;
        xout[r0 + 2]          = g_rhs[r0 + 2]          + al * a20;
        xout[NN + r0 + 2]     = g_rhs[NN + r0 + 2]     + al * a21;
        xout[2 * NN + r0 + 2] = g_rhs[2 * NN + r0 + 2] + al * a22;
        xout[r0 + 3]          = g_rhs[r0 + 3]          + al * a30;
        xout[NN + r0 + 3]     = g_rhs[NN + r0 + 3]     + al * a31;
        xout[2 * NN + r0 + 3] = g_rhs[2 * NN + r0 + 3] + al * a32;
    }
}

// ---------------- GCN layers -------------------------------------------------
// fused featfin + linear1
__global__ void k_lin1(const float* __restrict__ dv, const float* __restrict__ xfin,
                       const float* __restrict__ alphap,
                       const float* __restrict__ w1, const float* __restrict__ b1) {
    int id = blockIdx.x * blockDim.x + threadIdx.x;    // NN*F threads
    if (id < NN * F) {
        int i = id >> 7, f = id & 127;
        float s = 1.0f - *alphap;
        float c0 = dv[i];
        float c1 = s * xfin[i];
        float c2 = s * xfin[NN + i];
        float c3 = s * xfin[2 * NN + i];
        g_h1[id] = b1[f] + c0 * w1[f] + c1 * w1[F + f]
                         + c2 * w1[2 * F + f] + c3 * w1[3 * F + f];
    }
}

// aggregation, 2 nodes per 256-thread block, 8-wide edge unroll (MLP 8)
__global__ void __launch_bounds__(256) k_aggr1(const float* __restrict__ hin,
                                               float* __restrict__ hout) {
    int i = (blockIdx.x << 1) + (threadIdx.x >> 7);
    int f = threadIdx.x & 127;
    float d = g_dis[i];
    float acc = d * d * hin[i * F + f];                // self loop
    int e = g_off[i], end = g_off[i + 1];
    for (; e + 8 <= end; e += 8) {
        int   s0 = g_esrc[e],     s1 = g_esrc[e + 1], s2 = g_esrc[e + 2], s3 = g_esrc[e + 3];
        int   s4 = g_esrc[e + 4], s5 = g_esrc[e + 5], s6 = g_esrc[e + 6], s7 = g_esrc[e + 7];
        float n0 = g_enorm[e],     n1 = g_enorm[e + 1], n2 = g_enorm[e + 2], n3 = g_enorm[e + 3];
        float n4 = g_enorm[e + 4], n5 = g_enorm[e + 5], n6 = g_enorm[e + 6], n7 = g_enorm[e + 7];
        float h0 = hin[s0 * F + f], h1 = hin[s1 * F + f], h2 = hin[s2 * F + f], h3 = hin[s3 * F + f];
        float h4 = hin[s4 * F + f], h5 = hin[s5 * F + f], h6 = hin[s6 * F + f], h7 = hin[s7 * F + f];
        acc += n0 * h0 + n1 * h1 + n2 * h2 + n3 * h3
             + n4 * h4 + n5 * h5 + n6 * h6 + n7 * h7;
    }
    for (; e < end; ++e)
        acc += g_enorm[e] * hin[g_esrc[e] * F + f];
    hout[i * F + f] = fmaxf(acc, 0.0f);                // relu
}

__global__ void k_lin2(const float* __restrict__ hin, float* __restrict__ hout,
                       const float* __restrict__ w2, const float* __restrict__ b2) {
    int id = blockIdx.x * blockDim.x + threadIdx.x;
    if (id < NN * F) {
        int i = id >> 7, f = id & 127;
        const float* hr = hin + i * F;
        float acc = b2[f];
        #pragma unroll 8
        for (int gg = 0; gg < F; ++gg)
            acc += hr[gg] * w2[gg * F + f];
        hout[id] = acc;
    }
}

// aggregation (no relu) + final 128->2 projection, 2 nodes per 256-thread block
__global__ void __launch_bounds__(256) k_aggr2f(const float* __restrict__ hin,
                                                const float* __restrict__ wf,
                                                const float* __restrict__ bf,
                                                float* __restrict__ out) {
    __shared__ float sacc[2 * F];
    int half = threadIdx.x >> 7;
    int i = (blockIdx.x << 1) + half;
    int f = threadIdx.x & 127;
    float d = g_dis[i];
    float acc = d * d * hin[i * F + f];                // self loop
    int e = g_off[i], end = g_off[i + 1];
    for (; e + 8 <= end; e += 8) {
        int   s0 = g_esrc[e],     s1 = g_esrc[e + 1], s2 = g_esrc[e + 2], s3 = g_esrc[e + 3];
        int   s4 = g_esrc[e + 4], s5 = g_esrc[e + 5], s6 = g_esrc[e + 6], s7 = g_esrc[e + 7];
        float n0 = g_enorm[e],     n1 = g_enorm[e + 1], n2 = g_enorm[e + 2], n3 = g_enorm[e + 3];
        float n4 = g_enorm[e + 4], n5 = g_enorm[e + 5], n6 = g_enorm[e + 6], n7 = g_enorm[e + 7];
        float h0 = hin[s0 * F + f], h1 = hin[s1 * F + f], h2 = hin[s2 * F + f], h3 = hin[s3 * F + f];
        float h4 = hin[s4 * F + f], h5 = hin[s5 * F + f], h6 = hin[s6 * F + f], h7 = hin[s7 * F + f];
        acc += n0 * h0 + n1 * h1 + n2 * h2 + n3 * h3
             + n4 * h4 + n5 * h5 + n6 * h6 + n7 * h7;
    }
    for (; e < end; ++e)
        acc += g_enorm[e] * hin[g_esrc[e] * F + f];
    sacc[half * F + f] = acc;
    __syncthreads();

    int warp_in_half = (threadIdx.x >> 5) & 3, lane = threadIdx.x & 31;
    if (warp_in_half < 2) {                            // warp w computes output col w
        float a = 0.f;
        #pragma unroll
        for (int b = 0; b < 4; ++b) {
            int ff = lane + b * 32;
            a += sacc[half * F + ff] * wf[2 * ff + warp_in_half];
        }
        #pragma unroll
        for (int o = 16; o; o >>= 1)
            a += __shfl_down_sync(0xffffffffu, a, o);
        if (lane == 0)
            out[2 * i + warp_in_half] = a + bf[warp_in_half];
    }
}

// ---------------- driver -----------------------------------------------------
extern "C" void kernel_launch(void* const* d_in, const int* in_sizes, int n_in,
                              void* d_out, int out_size) {
    const float* alpha = (const float*)d_in[0];
    const float* L     = (const float*)d_in[1];
    const float* thr   = (const float*)d_in[2];
    const float* dv    = (const float*)d_in[3];
    const int*   ei    = (const int*)  d_in[4];
    const float* w1    = (const float*)d_in[5];
    const float* b1    = (const float*)d_in[6];
    const float* w2    = (const float*)d_in[7];
    const float* b2    = (const float*)d_in[8];
    const float* wf    = (const float*)d_in[9];
    const float* bf    = (const float*)d_in[10];
    float* out = (float*)d_out;
    int E = in_sizes[4] / 2;

    float *pa, *pb, *h1, *h2;
    cudaGetSymbolAddress((void**)&pa, g_xA);
    cudaGetSymbolAddress((void**)&pb, g_xB);
    cudaGetSymbolAddress((void**)&h1, g_h1);
    cudaGetSymbolAddress((void**)&h2, g_h2);

    // solve first (graph/CSR prep deferred so ncu -s 5 lands on k_richb)
    k_init<<<NN / 256, 256>>>();
    k_edges<<<(E + 255) / 256, 256>>>(ei, E);
    k_rhs<<<NN / 256, 256>>>(dv, thr);

    k_rich0<<<NN / 16, 128>>>(L, pa, pb, alpha);       // iter 0 + bf16 convert
    float* cur = pb;
    float* nxt = pa;
    for (int k = 1; k < K_TOT; ++k) {
        k_richb<<<NN / 32, 256>>>(cur, nxt, alpha);
        float* t = cur; cur = nxt; nxt = t;
    }
    // K_TOT=12 even -> final x in g_xA (cur == pa)

    // graph preprocessing for the GCN tail
    k_dis<<<NN / 256, 256>>>();
    k_scan<<<1, 1024>>>();
    k_fill<<<(E + 255) / 256, 256>>>(ei, E);

    k_lin1<<<(NN * F) / 256, 256>>>(dv, cur, alpha, w1, b1);
    k_aggr1<<<NN / 2, 256>>>(h1, h2);
    k_lin2<<<(NN * F) / 256, 256>>>(h2, h1, w2, b2);
    k_aggr2f<<<NN / 2, 256>>>(h1, wf, bf, out);
}